// round 9
// baseline (speedup 1.0000x reference)
#include <cuda_runtime.h>
#include <cuda_bf16.h>

// ---------------------------------------------------------------------------
// PointerNet additive attention, fused persistent kernel.
// B=4, Te=Td=512, E=256, D+E=512, H=64.
// out[b,d,t] = softmax_t( sum_h w2[h]*tanh(dec_t[b,d,h] + ctx_t[b,t,h]) )
//
// grid = 148 x 1024, block (b,ti) owns decoder rows [14ti,14ti+14).
// Role split (24 consumer warps / 8 producer warps):
//   consumers: load ctx tile, ctx projection (warps 0-15) -> g_ctxT,
//              release per-block flag, spin on source-block flags, then
//              tanh.approx score + softmax.
//              warps 0-15:  (t = tid, d 0..6)
//              warps 16-23: (t0 = 2k, t1 = 2k+1, d 7..13), float2 ctxT/out
//   producers: load dec tile, dec projection in four 16-h chunks -> dec_sh,
//              publish each chunk via bar.arrive. Starts immediately.
// ---------------------------------------------------------------------------

#define LOG2E 1.4426950408889634f

__device__ float    g_ctxT[4 * 64 * 512];   // [b][h][t]
__device__ unsigned g_startc[4];            // per-batch start tickets
__device__ unsigned g_done[4 * 37];         // per-block generation flags

// dynamic smem layout (floats)
#define CT_OFF 0          // ctx tile 14x256 = 3584
#define DT_OFF 3584       // dec tile 14x512 = 7168 -> 10752
#define CP_OFF 10752      // ctx partials 8 x 952 = 7616 -> 18368
#define PB_OFF 18368      // producer ping-pong 2 x 1792 = 3584 -> 21952
#define SM_FLOATS 21952   // 87808 bytes

__device__ __forceinline__ float ex2_approx(float x) {
    float y; asm("ex2.approx.f32 %0, %1;" : "=f"(y) : "f"(x)); return y;
}
__device__ __forceinline__ float tanh_approx(float x) {
    float y; asm("tanh.approx.f32 %0, %1;" : "=f"(y) : "f"(x)); return y;
}
__device__ __forceinline__ void bar_sync(int id, int cnt) {
    asm volatile("bar.sync %0, %1;" :: "r"(id), "r"(cnt) : "memory");
}
__device__ __forceinline__ void bar_arrive(int id, int cnt) {
    asm volatile("bar.arrive %0, %1;" :: "r"(id), "r"(cnt) : "memory");
}
__device__ __forceinline__ unsigned ld_acquire(const unsigned* p) {
    unsigned v;
    asm volatile("ld.acquire.gpu.global.u32 %0, [%1];" : "=r"(v) : "l"(p) : "memory");
    return v;
}
__device__ __forceinline__ void red_release_add(unsigned* p, unsigned v) {
    asm volatile("red.release.gpu.global.add.u32 [%0], %1;" :: "l"(p), "r"(v) : "memory");
}

__global__ __launch_bounds__(1024, 1) void fused_kernel(
    const float* __restrict__ ctx,   // [4,512,256]
    const float* __restrict__ dec,   // [4,512,512]
    const float* __restrict__ W1i,   // [256,64]
    const float* __restrict__ b1i,   // [64]
    const float* __restrict__ W1h,   // [512,64]
    const float* __restrict__ b1h,   // [64]
    const float* __restrict__ w2,    // [64]
    float* __restrict__ out)         // [4,512,512]
{
    extern __shared__ __align__(16) float sm[];
    __shared__ __align__(16) float dec_sh[896];   // 14 rows x 64 h
    __shared__ __align__(16) float w2_sh[64];     // pre-scaled by log2e
    __shared__ float red[168];                    // 7x16 (d0-6) + 7x8 (d7-13)
    __shared__ float inv_sh[14];
    __shared__ unsigned gen_sh;

    const int tid  = threadIdx.x;
    const int wid  = tid >> 5;
    const int lane = tid & 31;
    const int b    = blockIdx.x / 37;
    const int ti   = blockIdx.x % 37;
    const int d0   = ti * 14;

    if (wid < 24) {
        // ============================ CONSUMERS =============================
        if (tid == 0) gen_sh = atomicAdd(&g_startc[b], 1u) / 37u;

        // ---- load ctx tile + w2 ----
        {
            const float4* csrc = reinterpret_cast<const float4*>(ctx)
                               + ((size_t)(b << 9) + d0) * 64;
            float4* CT4 = reinterpret_cast<float4*>(sm + CT_OFF);
            for (int i = tid; i < 896; i += 768) {
                int r = i >> 6;
                CT4[i] = (d0 + r < 512) ? csrc[i] : make_float4(0.f,0.f,0.f,0.f);
            }
            if (tid < 64) w2_sh[tid] = w2[tid] * LOG2E;
        }

        // ---- ctx projection decomposition (warps 0-15) ----
        const int es   = wid & 7;                 // e-group (8-way)
        const int rg   = wid >> 3;                // row-group (2-way) [wid<16]
        const int half = lane >> 4;
        const int hq   = (lane & 15) << 2;        // h-quad base
        const int sub  = 2 * es + half;           // 16 subranges of 16 e
        const float* wp_c = W1i + (size_t)(sub * 16) * 64 + hq;

        float4 pw0, pw1, pw2, pw3;
        if (wid < 16) {                           // prefetch first e-group
            pw0 = *reinterpret_cast<const float4*>(wp_c + 0 * 64);
            pw1 = *reinterpret_cast<const float4*>(wp_c + 1 * 64);
            pw2 = *reinterpret_cast<const float4*>(wp_c + 2 * 64);
            pw3 = *reinterpret_cast<const float4*>(wp_c + 3 * 64);
        }
        bar_sync(7, 768);

        if (wid < 16) {
            float acc[7][4];
            #pragma unroll
            for (int r = 0; r < 7; r++)
                #pragma unroll
                for (int j = 0; j < 4; j++) acc[r][j] = 0.f;

            const float* xb = sm + CT_OFF + (rg * 7) * 256 + sub * 16;

            #pragma unroll
            for (int ec = 0; ec < 16; ec += 4) {
                float4 w0, w1, w2v, w3;
                if (ec == 0) { w0 = pw0; w1 = pw1; w2v = pw2; w3 = pw3; }
                else {
                    w0  = *reinterpret_cast<const float4*>(wp_c + (ec + 0) * 64);
                    w1  = *reinterpret_cast<const float4*>(wp_c + (ec + 1) * 64);
                    w2v = *reinterpret_cast<const float4*>(wp_c + (ec + 2) * 64);
                    w3  = *reinterpret_cast<const float4*>(wp_c + (ec + 3) * 64);
                }
                #pragma unroll
                for (int r = 0; r < 7; r++) {
                    float4 x = *reinterpret_cast<const float4*>(xb + r * 256 + ec);
                    acc[r][0] = fmaf(x.x, w0.x, acc[r][0]);
                    acc[r][1] = fmaf(x.x, w0.y, acc[r][1]);
                    acc[r][2] = fmaf(x.x, w0.z, acc[r][2]);
                    acc[r][3] = fmaf(x.x, w0.w, acc[r][3]);
                    acc[r][0] = fmaf(x.y, w1.x, acc[r][0]);
                    acc[r][1] = fmaf(x.y, w1.y, acc[r][1]);
                    acc[r][2] = fmaf(x.y, w1.z, acc[r][2]);
                    acc[r][3] = fmaf(x.y, w1.w, acc[r][3]);
                    acc[r][0] = fmaf(x.z, w2v.x, acc[r][0]);
                    acc[r][1] = fmaf(x.z, w2v.y, acc[r][1]);
                    acc[r][2] = fmaf(x.z, w2v.z, acc[r][2]);
                    acc[r][3] = fmaf(x.z, w2v.w, acc[r][3]);
                    acc[r][0] = fmaf(x.w, w3.x, acc[r][0]);
                    acc[r][1] = fmaf(x.w, w3.y, acc[r][1]);
                    acc[r][2] = fmaf(x.w, w3.z, acc[r][2]);
                    acc[r][3] = fmaf(x.w, w3.w, acc[r][3]);
                }
            }

            #pragma unroll
            for (int r = 0; r < 7; r++)
                #pragma unroll
                for (int j = 0; j < 4; j++)
                    acc[r][j] += __shfl_xor_sync(0xffffffffu, acc[r][j], 16);

            if (half == 0) {
                float* pp = sm + CP_OFF + es * 952 + (rg * 7) * 68 + hq;
                #pragma unroll
                for (int r = 0; r < 7; r++)
                    *reinterpret_cast<float4*>(pp + r * 68) =
                        make_float4(acc[r][0], acc[r][1], acc[r][2], acc[r][3]);
            }
        }
        bar_sync(7, 768);

        // ---- reduce 8 partials -> g_ctxT (t-major: coalesced stores) ----
        for (int o = tid; o < 896; o += 768) {
            const int h = o / 14, r = o - h * 14;
            float s = 0.f;
            #pragma unroll
            for (int e8 = 0; e8 < 8; e8++)
                s += sm[CP_OFF + e8 * 952 + r * 68 + h];
            s += b1i[h];
            const int t = d0 + r;
            if (t < 512) g_ctxT[((b << 6) + h) * 512 + t] = s;
        }
        bar_sync(7, 768);
        if (tid == 0) red_release_add(&g_done[b * 37 + ti], 1u);

        const unsigned target = gen_sh + 1u;

        if (wid < 16) {
            // ---------------- group 1: t = tid, d 0..6 ----------------
            const int t = tid;
            while (ld_acquire(&g_done[b * 37 + (t / 14)]) < target) {}

            const float* cptr = g_ctxT + (size_t)(b << 6) * 512 + t;
            float acc[7];
            #pragma unroll
            for (int d = 0; d < 7; d++) acc[d] = 0.f;

            float c0 = cptr[0 * 512];
            float c1 = cptr[1 * 512];
            float c2 = cptr[2 * 512];
            float c3 = cptr[3 * 512];

            #pragma unroll 1
            for (int c = 0; c < 4; c++) {
                bar_sync(1 + c, 1024);
                #pragma unroll
                for (int hh = 0; hh < 16; hh += 4) {
                    const int h = (c << 4) + hh;
                    const int hn = (h + 4) & 63;
                    float n0 = cptr[(hn + 0) * 512];
                    float n1 = cptr[(hn + 1) * 512];
                    float n2 = cptr[(hn + 2) * 512];
                    float n3 = cptr[(hn + 3) * 512];

                    float4 w4 = *reinterpret_cast<const float4*>(&w2_sh[h]);
                    #pragma unroll
                    for (int d = 0; d < 7; d++) {
                        float4 dv = *reinterpret_cast<const float4*>(&dec_sh[(d << 6) + h]);
                        acc[d] = fmaf(w4.x, tanh_approx(dv.x + c0), acc[d]);
                        acc[d] = fmaf(w4.y, tanh_approx(dv.y + c1), acc[d]);
                        acc[d] = fmaf(w4.z, tanh_approx(dv.z + c2), acc[d]);
                        acc[d] = fmaf(w4.w, tanh_approx(dv.w + c3), acc[d]);
                    }
                    c0 = n0; c1 = n1; c2 = n2; c3 = n3;
                }
            }

            float ex[7];
            #pragma unroll
            for (int d = 0; d < 7; d++) {
                float e = ex2_approx(acc[d]);
                ex[d] = e;
                float s = e;
                #pragma unroll
                for (int off = 16; off; off >>= 1)
                    s += __shfl_xor_sync(0xffffffffu, s, off);
                if (lane == 0) red[d * 16 + wid] = s;
            }
            bar_sync(7, 768);
            if (wid < 14) {
                float v;
                if (wid < 7) {
                    v = (lane < 16) ? red[wid * 16 + lane] : 0.f;
                    #pragma unroll
                    for (int off = 8; off; off >>= 1)
                        v += __shfl_xor_sync(0xffffffffu, v, off);
                } else {
                    v = (lane < 8) ? red[112 + (wid - 7) * 8 + lane] : 0.f;
                    #pragma unroll
                    for (int off = 4; off; off >>= 1)
                        v += __shfl_xor_sync(0xffffffffu, v, off);
                }
                if (lane == 0) inv_sh[wid] = 1.0f / v;
            }
            bar_sync(7, 768);
            #pragma unroll
            for (int d = 0; d < 7; d++) {
                if (d0 + d < 512)
                    out[((size_t)(b << 9) + d0 + d) * 512 + t] = ex[d] * inv_sh[d];
            }
        } else {
            // ------------- group 2: t0 = 2k, t1 = 2k+1, d 7..13 -------------
            const int k  = tid - 512;             // 0..255
            const int t0 = 2 * k;
            while (ld_acquire(&g_done[b * 37 + (t0 / 14)]) < target) {}
            while (ld_acquire(&g_done[b * 37 + ((t0 + 1) / 14)]) < target) {}

            const float* cptr = g_ctxT + (size_t)(b << 6) * 512 + t0;
            float acc0[7], acc1[7];
            #pragma unroll
            for (int d = 0; d < 7; d++) { acc0[d] = 0.f; acc1[d] = 0.f; }

            float2 c0 = *reinterpret_cast<const float2*>(cptr + 0 * 512);
            float2 c1 = *reinterpret_cast<const float2*>(cptr + 1 * 512);
            float2 c2 = *reinterpret_cast<const float2*>(cptr + 2 * 512);
            float2 c3 = *reinterpret_cast<const float2*>(cptr + 3 * 512);

            #pragma unroll 1
            for (int c = 0; c < 4; c++) {
                bar_sync(1 + c, 1024);
                #pragma unroll
                for (int hh = 0; hh < 16; hh += 4) {
                    const int h = (c << 4) + hh;
                    const int hn = (h + 4) & 63;
                    float2 n0 = *reinterpret_cast<const float2*>(cptr + (hn + 0) * 512);
                    float2 n1 = *reinterpret_cast<const float2*>(cptr + (hn + 1) * 512);
                    float2 n2 = *reinterpret_cast<const float2*>(cptr + (hn + 2) * 512);
                    float2 n3 = *reinterpret_cast<const float2*>(cptr + (hn + 3) * 512);

                    float4 w4 = *reinterpret_cast<const float4*>(&w2_sh[h]);
                    #pragma unroll
                    for (int d = 0; d < 7; d++) {
                        float4 dv = *reinterpret_cast<const float4*>(&dec_sh[((d + 7) << 6) + h]);
                        acc0[d] = fmaf(w4.x, tanh_approx(dv.x + c0.x), acc0[d]);
                        acc1[d] = fmaf(w4.x, tanh_approx(dv.x + c0.y), acc1[d]);
                        acc0[d] = fmaf(w4.y, tanh_approx(dv.y + c1.x), acc0[d]);
                        acc1[d] = fmaf(w4.y, tanh_approx(dv.y + c1.y), acc1[d]);
                        acc0[d] = fmaf(w4.z, tanh_approx(dv.z + c2.x), acc0[d]);
                        acc1[d] = fmaf(w4.z, tanh_approx(dv.z + c2.y), acc1[d]);
                        acc0[d] = fmaf(w4.w, tanh_approx(dv.w + c3.x), acc0[d]);
                        acc1[d] = fmaf(w4.w, tanh_approx(dv.w + c3.y), acc1[d]);
                    }
                    c0 = n0; c1 = n1; c2 = n2; c3 = n3;
                }
            }

            float ex0[7], ex1[7];
            #pragma unroll
            for (int d = 0; d < 7; d++) {
                float e0 = ex2_approx(acc0[d]);
                float e1 = ex2_approx(acc1[d]);
                ex0[d] = e0; ex1[d] = e1;
                float s = e0 + e1;
                #pragma unroll
                for (int off = 16; off; off >>= 1)
                    s += __shfl_xor_sync(0xffffffffu, s, off);
                if (lane == 0) red[112 + d * 8 + (wid - 16)] = s;
            }
            bar_sync(7, 768);
            // final inverse handled by warps 0-13 (group 1 path)
            bar_sync(7, 768);
            #pragma unroll
            for (int d = 0; d < 7; d++) {
                const int row = d0 + 7 + d;
                if (row < 512) {
                    float inv = inv_sh[7 + d];
                    *reinterpret_cast<float2*>(out + (size_t)(b << 9) * 512
                                               + (size_t)row * 512 + t0) =
                        make_float2(ex0[d] * inv, ex1[d] * inv);
                }
            }
        }
    } else {
        // ============================ PRODUCERS =============================
        const int q     = tid - 768;              // 0..255
        const int p     = wid - 24;               // 0..7: e-range [64p,64p+64)
        const int phalf = lane >> 4;              // 32-e subrange
        const int hl    = lane & 15;              // h within chunk

        // ---- load dec tile ----
        {
            const float4* dsrc = reinterpret_cast<const float4*>(dec)
                               + ((size_t)(b << 9) + d0) * 128;
            float4* DT4 = reinterpret_cast<float4*>(sm + DT_OFF);
            #pragma unroll
            for (int i = q; i < 1792; i += 256) {
                int r = i >> 7;
                DT4[i] = (d0 + r < 512) ? dsrc[i] : make_float4(0.f,0.f,0.f,0.f);
            }
        }
        bar_sync(6, 256);

        const int e0 = p * 64 + phalf * 32;
        const float* xb = sm + DT_OFF + e0;

        #pragma unroll 1
        for (int c = 0; c < 4; c++) {
            const int hbase = c << 4;
            float acc[14];
            #pragma unroll
            for (int r = 0; r < 14; r++) acc[r] = 0.f;

            const float* wp = W1h + (size_t)e0 * 64 + hbase + hl;
            #pragma unroll
            for (int ec = 0; ec < 32; ec += 4) {
                float w0 = wp[(ec + 0) * 64];
                float w1 = wp[(ec + 1) * 64];
                float w2v = wp[(ec + 2) * 64];
                float w3 = wp[(ec + 3) * 64];
                #pragma unroll
                for (int r = 0; r < 14; r++) {
                    float4 x = *reinterpret_cast<const float4*>(xb + r * 512 + ec);
                    acc[r] = fmaf(x.x, w0,
                             fmaf(x.y, w1,
                             fmaf(x.z, w2v,
                             fmaf(x.w, w3, acc[r]))));
                }
            }
            #pragma unroll
            for (int r = 0; r < 14; r++)
                acc[r] += __shfl_xor_sync(0xffffffffu, acc[r], 16);

            float* pb = sm + PB_OFF + (c & 1) * 1792;
            if (phalf == 0) {
                #pragma unroll
                for (int r = 0; r < 14; r++)
                    pb[p * 224 + r * 16 + hl] = acc[r];
            }
            bar_sync(6, 256);
            if (q < 224) {
                const int r = q >> 4, hh = q & 15;
                float s = 0.f;
                #pragma unroll
                for (int p8 = 0; p8 < 8; p8++) s += pb[p8 * 224 + q];
                dec_sh[(r << 6) + hbase + hh] = s + b1h[hbase + hh];
            }
            bar_arrive(1 + c, 1024);               // publish chunk c
        }
        // producers exit
    }
}

// ---------------------------------------------------------------------------
extern "C" void kernel_launch(void* const* d_in, const int* in_sizes, int n_in,
                              void* d_out, int out_size)
{
    const float* ctx  = (const float*)d_in[0];
    const float* dec  = (const float*)d_in[1];
    const float* W1i  = (const float*)d_in[2];
    const float* b1i  = (const float*)d_in[3];
    const float* W1h  = (const float*)d_in[4];
    const float* b1h  = (const float*)d_in[5];
    const float* w2   = (const float*)d_in[6];
    float* out = (float*)d_out;

    const int smem_bytes = SM_FLOATS * sizeof(float);   // ~88 KB
    cudaFuncSetAttribute(fused_kernel,
                         cudaFuncAttributeMaxDynamicSharedMemorySize,
                         smem_bytes);
    fused_kernel<<<148, 1024, smem_bytes>>>(ctx, dec, W1i, b1i, W1h, b1h, w2, out);
}